// round 15
// baseline (speedup 1.0000x reference)
#include <cuda_runtime.h>
#include <cuda_fp16.h>
#include <cstdint>
#include <math.h>

#define B_ROWS 16384
#define DDIM   512
#define EEXP   16
#define HDIM   256
#define LOUT   64

// ---------------- device scratch (allocation-free rule) ----------------
__device__ float  g_gates[B_ROWS * EEXP];
__device__ int    g_counts[EEXP];
__device__ int    g_rows[EEXP * B_ROWS];
__device__ __half g_Xh [B_ROWS * DDIM];        // x hi, fp16
__device__ __half g_Xlo[B_ROWS * DDIM];        // (x - hi)*2048, fp16
__device__ __half g_W1T[EEXP * HDIM * DDIM];   // [E][H][D], fp16
__device__ __half g_W2T[EEXP * LOUT * HDIM];   // [E][L][H], fp16
__device__ __half g_WcHi[32 * DDIM];           // gating weights [32 cols][512], hi
__device__ __half g_WcLo[32 * DDIM];           // (w - hi)*2048

// ---------------- helpers ----------------
__device__ __forceinline__ uint32_t smem_u32_of(const void* p) {
    uint32_t a;
    asm("{ .reg .u64 t; cvta.to.shared.u64 t, %1; cvt.u32.u64 %0, t; }" : "=r"(a) : "l"(p));
    return a;
}
__device__ __forceinline__ float tanh_fast(float x) {
    float e = __expf(2.f * x);
    return 1.f - __fdividef(2.f, e + 1.f);
}
__device__ __forceinline__ float softplusf(float z) {
    return (z > 0.f) ? (z + log1pf(expf(-z))) : log1pf(expf(z));
}
__device__ __forceinline__ void cp16(uint32_t dst, const void* src) {
    asm volatile("cp.async.ca.shared.global [%0], [%1], 16;" :: "r"(dst), "l"(src));
}
#define CP_COMMIT() asm volatile("cp.async.commit_group;" ::: "memory")
#define CP_WAIT(n)  asm volatile("cp.async.wait_group %0;" :: "n"(n) : "memory")

#define LDMX4(r0, r1, r2, r3, addr) \
    asm volatile("ldmatrix.sync.aligned.m8n8.x4.shared.b16 {%0,%1,%2,%3}, [%4];" \
                 : "=r"(r0), "=r"(r1), "=r"(r2), "=r"(r3) : "r"(addr))

__device__ __forceinline__ void mma_f16(float* c, const uint32_t* a, const uint32_t* b) {
    asm volatile(
        "mma.sync.aligned.m16n8k16.row.col.f32.f16.f16.f32 "
        "{%0,%1,%2,%3}, {%4,%5,%6,%7}, {%8,%9}, {%0,%1,%2,%3};"
        : "+f"(c[0]), "+f"(c[1]), "+f"(c[2]), "+f"(c[3])
        : "r"(a[0]), "r"(a[1]), "r"(a[2]), "r"(a[3]), "r"(b[0]), "r"(b[1]));
}

// ---------------------------------------------------------------------------
// prep_all: convx split + W1/W2 transposes + gating-weight split + counter
// reset, fused into one launch (block-range switch).
// ---------------------------------------------------------------------------
__device__ __forceinline__ void transpose_tile(const float* __restrict__ s,
                                               __half* __restrict__ d,
                                               int R, int C, int c0, int r0,
                                               float t[32][33], int tx, int ty)
{
    #pragma unroll
    for (int i = 0; i < 32; i += 8)
        t[ty + i][tx] = s[(size_t)(r0 + ty + i) * C + c0 + tx];
    __syncthreads();
    #pragma unroll
    for (int i = 0; i < 32; i += 8)
        d[(size_t)(c0 + ty + i) * R + r0 + tx] = __float2half_rn(t[tx][ty + i]);
}

__global__ __launch_bounds__(256) void prep_all_kernel(
    const float4* __restrict__ x4,
    const float* __restrict__ wg, const float* __restrict__ wn,
    const float* __restrict__ W1, const float* __restrict__ W2)
{
    __shared__ float t[32][33];
    const int b   = blockIdx.x;
    const int tid = threadIdx.x;
    const int tx  = tid & 31;
    const int ty  = tid >> 5;

    if (b < 8192) {
        if (b == 0 && tid < EEXP) g_counts[tid] = 0;
        int i = b * 256 + tid;
        float4 v = x4[i];
        __half hx = __float2half_rn(v.x), hy = __float2half_rn(v.y);
        __half hz = __float2half_rn(v.z), hw = __float2half_rn(v.w);
        __half2* hi = (__half2*)g_Xh;
        __half2* lo = (__half2*)g_Xlo;
        hi[2 * i]     = __halves2half2(hx, hy);
        hi[2 * i + 1] = __halves2half2(hz, hw);
        lo[2 * i]     = __floats2half2_rn((v.x - __half2float(hx)) * 2048.f,
                                          (v.y - __half2float(hy)) * 2048.f);
        lo[2 * i + 1] = __floats2half2_rn((v.z - __half2float(hz)) * 2048.f,
                                          (v.w - __half2float(hw)) * 2048.f);
    } else if (b < 10240) {
        int bb = b - 8192;
        int e = bb >> 7, rem = bb & 127;
        int c0 = (rem & 7) * 32, r0 = (rem >> 3) * 32;
        transpose_tile(W1 + (size_t)e * DDIM * HDIM,
                       g_W1T + (size_t)e * HDIM * DDIM,
                       DDIM, HDIM, c0, r0, t, tx, ty);
    } else if (b < 10496) {
        int bb = b - 10240;
        int e = bb >> 4, rem = bb & 15;
        int c0 = (rem & 1) * 32, r0 = (rem >> 1) * 32;
        transpose_tile(W2 + (size_t)e * HDIM * LOUT,
                       g_W2T + (size_t)e * LOUT * HDIM,
                       HDIM, LOUT, c0, r0, t, tx, ty);
    } else {
        int idx = (b - 10496) * 256 + tid;       // 0..16383
        int j = idx >> 9, d = idx & 511;
        float v = (j < 16) ? wg[d * 16 + j] : wn[d * 16 + (j - 16)];
        __half h = __float2half_rn(v);
        g_WcHi[j * 512 + d] = h;
        g_WcLo[j * 512 + d] = __float2half_rn((v - __half2float(h)) * 2048.f);
    }
}

// ---------------------------------------------------------------------------
// Sparse zerofill (after gating): zero out[s,:] wherever g_gates[s]==0.
// ---------------------------------------------------------------------------
__global__ __launch_bounds__(256) void zerofill_kernel(float4* __restrict__ out)
{
    int gidx = blockIdx.x * 256 + threadIdx.x;
    int s = gidx >> 4;
    int q = gidx & 15;
    if (g_gates[s] == 0.f)
        out[(size_t)s * 16 + q] = make_float4(0.f, 0.f, 0.f, 0.f);
}

// ---------------------------------------------------------------------------
// Gating v8 (unchanged from R14): split-fp16 compensated tensor-core GEMM,
// 64 rows/CTA, 256 CTAs, 2 CTAs/SM; fp32-exact epilogue + compaction.
// ---------------------------------------------------------------------------
#define GB_HI   0               // 32*520*2 = 33280
#define GB_LO   33280
#define GA_HI0  66560           // 64*40*2 = 5120 each
#define GA_HI1  71680
#define GA_LO0  76800
#define GA_LO1  81920
#define G_SC    66560           // overlay after GEMM: 64*34*4 = 8704
#define G_LIST  75264           // 16*64 ints = 4096
#define G_CNT   79360
#define G_BASE  79424
#define G2_SMEM 87040

#define GLB  40
#define GLW  520
#define INV2048 4.8828125e-4f

__global__ __launch_bounds__(256, 2) void gating_kernel(const float* __restrict__ noise)
{
    extern __shared__ char gsm[];
    const int tid  = threadIdx.x;
    const int wid  = tid >> 5;
    const int lane = tid & 31;
    const int g    = lane >> 2;
    const int tig  = lane & 3;
    const int m0   = blockIdx.x * 64;
    const uint32_t sb = smem_u32_of(gsm);

    const int wm = wid >> 1;
    const int wn = wid & 1;

    const uint32_t offA  = (uint32_t)((lane & 15) * (GLB * 2) + (lane >> 4) * 16);
    const uint32_t offBG = (uint32_t)(((lane & 7) + ((lane >> 4) & 1) * 8) * (GLW * 2) + ((lane >> 3) & 1) * 16);

    #pragma unroll
    for (int t = 0; t < 8; t++) {
        int id = tid + t * 256;
        int r = id >> 6, q = id & 63;
        cp16(sb + GB_HI + (uint32_t)(r * (GLW * 2) + q * 16), g_WcHi + r * 512 + q * 8);
        cp16(sb + GB_LO + (uint32_t)(r * (GLW * 2) + q * 16), g_WcLo + r * 512 + q * 8);
    }

    auto loadA = [&](int c, int buf) {
        uint32_t hB = sb + (buf ? GA_HI1 : GA_HI0);
        uint32_t lB = sb + (buf ? GA_LO1 : GA_LO0);
        int r = tid >> 2, q = tid & 3;
        cp16(hB + (uint32_t)(r * (GLB * 2) + q * 16),
             g_Xh  + (size_t)(m0 + r) * DDIM + c * 32 + q * 8);
        cp16(lB + (uint32_t)(r * (GLB * 2) + q * 16),
             g_Xlo + (size_t)(m0 + r) * DDIM + c * 32 + q * 8);
    };

    loadA(0, 0);
    CP_COMMIT();

    float acc[2][4], accC[2][4];
    #pragma unroll
    for (int j = 0; j < 2; j++)
        #pragma unroll
        for (int q = 0; q < 4; q++) { acc[j][q] = 0.f; accC[j][q] = 0.f; }

    for (int c = 0; c < 16; c++) {
        int buf = c & 1;
        CP_WAIT(0);
        __syncthreads();
        if (c + 1 < 16) { loadA(c + 1, buf ^ 1); CP_COMMIT(); }

        uint32_t aH = sb + (buf ? GA_HI1 : GA_HI0);
        uint32_t aL = sb + (buf ? GA_LO1 : GA_LO0);

        #pragma unroll
        for (int ks = 0; ks < 32; ks += 16) {
            int kg = c * 32 + ks;
            uint32_t ah[4], al[4], bh[4], bl[4];
            uint32_t oa = (uint32_t)(((wm * 16) * GLB + ks) * 2) + offA;
            LDMX4(ah[0], ah[1], ah[2], ah[3], aH + oa);
            LDMX4(al[0], al[1], al[2], al[3], aL + oa);
            uint32_t ob = (uint32_t)(((wn * 16) * GLW + kg) * 2) + offBG;
            LDMX4(bh[0], bh[1], bh[2], bh[3], sb + GB_HI + ob);
            LDMX4(bl[0], bl[1], bl[2], bl[3], sb + GB_LO + ob);
            mma_f16(acc [0], ah, bh);
            mma_f16(acc [1], ah, bh + 2);
            mma_f16(accC[0], ah, bl);
            mma_f16(accC[1], ah, bl + 2);
            mma_f16(accC[0], al, bh);
            mma_f16(accC[1], al, bh + 2);
        }
    }
    __syncthreads();

    float* sC    = (float*)(gsm + G_SC);
    int*   sList = (int*)(gsm + G_LIST);
    int*   sCnt  = (int*)(gsm + G_CNT);
    int*   sBase = (int*)(gsm + G_BASE);

    {
        int r0 = wm * 16 + g;
        #pragma unroll
        for (int nb = 0; nb < 2; nb++) {
            int cc = wn * 16 + nb * 8 + 2 * tig;
            float2 v0, v1;
            v0.x = acc[nb][0] + accC[nb][0] * INV2048;
            v0.y = acc[nb][1] + accC[nb][1] * INV2048;
            v1.x = acc[nb][2] + accC[nb][2] * INV2048;
            v1.y = acc[nb][3] + accC[nb][3] * INV2048;
            *(float2*)&sC[r0 * 34 + cc]       = v0;
            *(float2*)&sC[(r0 + 8) * 34 + cc] = v1;
        }
    }
    if (tid < EEXP) sCnt[tid] = 0;
    __syncthreads();

    if (tid < 64) {
        int r = m0 + tid;
        float lg[16], p[16];
        float mx = -1e30f;
        #pragma unroll
        for (int j = 0; j < 16; j++) {
            float cl = sC[tid * 34 + j];
            float sd = softplusf(sC[tid * 34 + 16 + j]) + 0.01f;
            lg[j] = fmaf(noise[(size_t)r * EEXP + j], sd, cl);
            mx = fmaxf(mx, lg[j]);
        }
        float s = 0.f;
        #pragma unroll
        for (int j = 0; j < 16; j++) { p[j] = expf(lg[j] - mx); s += p[j]; }
        float s2 = 0.f;
        #pragma unroll
        for (int j = 0; j < 16; j++) { p[j] = p[j] / s; s2 += p[j]; }
        float meanw = s2 * (1.f / 16.f) - 1e-8f;
        float gs = 0.f;
        #pragma unroll
        for (int j = 0; j < 16; j++) {
            p[j] = (p[j] >= meanw) ? p[j] : 0.f;
            gs += p[j];
        }
        #pragma unroll
        for (int j = 0; j < 16; j++) {
            g_gates[(size_t)r * EEXP + j] = p[j] / gs;
            if (p[j] > 0.f) {
                int idx = atomicAdd(&sCnt[j], 1);
                sList[j * 64 + idx] = r;
            }
        }
    }
    __syncthreads();

    if (tid < EEXP) sBase[tid] = atomicAdd(&g_counts[tid], sCnt[tid]);
    __syncthreads();

    for (int j = 0; j < EEXP; j++) {
        int n = sCnt[j], b = sBase[j];
        for (int i = tid; i < n; i += 256)
            g_rows[j * B_ROWS + b + i] = sList[j * 64 + i];
    }
}

// ---------------------------------------------------------------------------
// Fused expert MLP v9: 8 warps / 256 threads, 64x64 warp tiles (2x4 grid).
// SMEM bytes per HMMA cut 33% vs v7; 32-deep HMMA ILP per warp.
// Same 3-stage cp.async pipeline, resident W2, barrier-free phase 2.
// ---------------------------------------------------------------------------
#define SM_H     0              // 128*264*2 = 67584
#define SM_A0    67584          // 128*40*2  = 10240 (x3)
#define SM_B0    98304          // 256*40*2  = 20480 (x3)
#define SM_W2    159744         // 64*264*2  = 33792
#define SM_BIAS  193536         // 256f + 64f = 1280
#define SM_ROWS  194816         // 128 ints = 512
#define SMEM_MOE 195328

#define LDK1 40
#define LDH  264
#define LDW2 264

__global__ __launch_bounds__(256, 1) void moe_kernel(
    const float* __restrict__ b1, const float* __restrict__ b2,
    float* __restrict__ out)
{
    extern __shared__ char smem[];
    __half* sH    = (__half*)(smem + SM_H);
    float* sBias1 = (float*)(smem + SM_BIAS);
    float* sBias2 = sBias1 + HDIM;
    int*   sRows  = (int*)(smem + SM_ROWS);

    const int e   = blockIdx.y;
    const int m0  = blockIdx.x * 128;
    const int cnt = g_counts[e];
    if (m0 >= cnt) return;

    const int tid  = threadIdx.x;
    const int wid  = tid >> 5;
    const int lane = tid & 31;
    const int g    = lane >> 2;
    const int tig  = lane & 3;

    const uint32_t smem_b = smem_u32_of(smem);

    const __half* w1e = g_W1T + (size_t)e * HDIM * DDIM;
    const __half* w2e = g_W2T + (size_t)e * LOUT * HDIM;

    if (tid < 128) {
        int p = m0 + tid;
        sRows[tid] = g_rows[e * B_ROWS + (p < cnt ? p : cnt - 1)];
    }
    sBias1[tid] = b1[(size_t)e * HDIM + tid];     // 256 threads = HDIM exactly
    if (tid < LOUT) sBias2[tid] = b2[(size_t)e * LOUT + tid];
    __syncthreads();   // sRows visible before gathered cp.async

    const uint32_t offA  = (uint32_t)((lane & 15) * (LDK1 * 2) + (lane >> 4) * 16);
    const uint32_t offB  = (uint32_t)(((lane & 7) + ((lane >> 4) & 1) * 8) * (LDK1 * 2) + ((lane >> 3) & 1) * 16);
    const uint32_t offA2 = (uint32_t)((lane & 15) * (LDH * 2) + (lane >> 4) * 16);
    const uint32_t offB2 = (uint32_t)(((lane & 7) + ((lane >> 4) & 1) * 8) * (LDW2 * 2) + ((lane >> 3) & 1) * 16);

    // ---------------- phase 1: 2x4 warp grid, 64x64 warp tiles ----------------
    const int wm = wid >> 2;      // 0..1 : rows 64*wm
    const int wn = wid & 3;       // 0..3 : cols 64*wn

    float acc[4][8][4];
    #pragma unroll
    for (int i = 0; i < 4; i++)
        #pragma unroll
        for (int j = 0; j < 8; j++)
            #pragma unroll
            for (int q = 0; q < 4; q++) acc[i][j][q] = 0.f;

    auto load_chunk1 = [&](int c, int buf) {
        uint32_t aBase = smem_b + SM_A0 + buf * 10240;
        uint32_t bBase = smem_b + SM_B0 + buf * 20480;
        #pragma unroll
        for (int t = 0; t < 2; t++) {   // A: 512 cp16
            int id = tid + t * 256;
            int r = id >> 2, q = id & 3;
            const __half* src = g_Xh + (size_t)sRows[r] * DDIM + c * 32 + q * 8;
            cp16(aBase + (uint32_t)(r * (LDK1 * 2) + q * 16), src);
        }
        #pragma unroll
        for (int t = 0; t < 4; t++) {   // B: 1024 cp16
            int id = tid + t * 256;
            int r = id >> 2, q = id & 3;
            cp16(bBase + (uint32_t)(r * (LDK1 * 2) + q * 16),
                 w1e + (size_t)r * DDIM + c * 32 + q * 8);
        }
        CP_COMMIT();
    };

    load_chunk1(0, 0);
    load_chunk1(1, 1);

    for (int c = 0; c < 16; c++) {
        int buf = c % 3;
        CP_WAIT(1);
        __syncthreads();
        if (c + 2 < 16) {
            load_chunk1(c + 2, (c + 2) % 3);
        } else if (c + 2 == 16) {
            uint32_t wBase = smem_b + SM_W2;
            #pragma unroll
            for (int t = 0; t < 8; t++) {   // W2: 2048 cp16
                int id = tid + t * 256;
                int r = id >> 5, q = id & 31;
                cp16(wBase + (uint32_t)(r * (LDW2 * 2) + q * 16),
                     w2e + (size_t)r * HDIM + q * 8);
            }
            CP_COMMIT();
        }

        const uint32_t aB = smem_b + SM_A0 + buf * 10240;
        const uint32_t bB = smem_b + SM_B0 + buf * 20480;

        #pragma unroll
        for (int ks = 0; ks < 32; ks += 16) {
            uint32_t af[4][4];
            #pragma unroll
            for (int i = 0; i < 4; i++) {
                uint32_t ad = aB + (uint32_t)(((wm * 64 + i * 16) * LDK1 + ks) * 2) + offA;
                LDMX4(af[i][0], af[i][1], af[i][2], af[i][3], ad);
            }
            uint32_t bf[8][2];
            #pragma unroll
            for (int j2 = 0; j2 < 4; j2++) {
                uint32_t bd = bB + (uint32_t)(((wn * 64 + j2 * 16) * LDK1 + ks) * 2) + offB;
                LDMX4(bf[2 * j2][0], bf[2 * j2][1], bf[2 * j2 + 1][0], bf[2 * j2 + 1][1], bd);
            }
            #pragma unroll
            for (int i = 0; i < 4; i++)
                #pragma unroll
                for (int j = 0; j < 8; j++)
                    mma_f16(acc[i][j], af[i], bf[j]);
        }
    }

    // ---- tanh(C1 + b1) -> sH (fp16) ----
    #pragma unroll
    for (int i = 0; i < 4; i++) {
        int r0 = wm * 64 + i * 16 + g;
        #pragma unroll
        for (int j = 0; j < 8; j++) {
            int cc = wn * 64 + j * 8 + 2 * tig;
            float bb0 = sBias1[cc], bb1 = sBias1[cc + 1];
            *(__half2*)&sH[r0 * LDH + cc] =
                __floats2half2_rn(tanh_fast(acc[i][j][0] + bb0), tanh_fast(acc[i][j][1] + bb1));
            *(__half2*)&sH[(r0 + 8) * LDH + cc] =
                __floats2half2_rn(tanh_fast(acc[i][j][2] + bb0), tanh_fast(acc[i][j][3] + bb1));
        }
    }
    CP_WAIT(0);          // W2 resident
    __syncthreads();     // sH visible; phase 2 barrier-free

    // ---------------- phase 2: 4x2 warp grid, 32x32 warp tiles, K=256 -------
    const int wm2 = wid >> 1;     // 0..3 : rows 32*wm2
    const int wn2 = wid & 1;      // 0..1 : cols 32*wn2

    float acc2[2][4][4];
    #pragma unroll
    for (int i = 0; i < 2; i++)
        #pragma unroll
        for (int j = 0; j < 4; j++)
            #pragma unroll
            for (int q = 0; q < 4; q++) acc2[i][j][q] = 0.f;

    const uint32_t hB = smem_b + SM_H;
    const uint32_t wB = smem_b + SM_W2;

    #pragma unroll
    for (int ks = 0; ks < 256; ks += 16) {
        uint32_t af[2][4];
        #pragma unroll
        for (int i = 0; i < 2; i++) {
            uint32_t ad = hB + (uint32_t)(((wm2 * 32 + i * 16) * LDH + ks) * 2) + offA2;
            LDMX4(af[i][0], af[i][1], af[i][2], af[i][3], ad);
        }
        uint32_t bf[4][2];
        #pragma unroll
        for (int j2 = 0; j2 < 2; j2++) {
            uint32_t bd = wB + (uint32_t)(((wn2 * 32 + j2 * 16) * LDW2 + ks) * 2) + offB2;
            LDMX4(bf[2 * j2][0], bf[2 * j2][1], bf[2 * j2 + 1][0], bf[2 * j2 + 1][1], bd);
        }
        #pragma unroll
        for (int i = 0; i < 2; i++)
            #pragma unroll
            for (int j = 0; j < 4; j++)
                mma_f16(acc2[i][j], af[i], bf[j]);
    }

    // ---- epilogue: scatter out[row, e] = gate * (C2 + b2) ----
    #pragma unroll
    for (int i = 0; i < 2; i++) {
        int p0 = wm2 * 32 + i * 16 + g;
        #pragma unroll
        for (int h = 0; h < 2; h++) {
            int p = p0 + h * 8;
            if (m0 + p < cnt) {
                int row = sRows[p];
                float gate = g_gates[(size_t)row * EEXP + e];
                float* op = out + ((size_t)row * EEXP + e) * LOUT;
                #pragma unroll
                for (int j = 0; j < 4; j++) {
                    int cc = wn2 * 32 + j * 8 + 2 * tig;
                    float2 o;
                    o.x = (acc2[i][j][2 * h + 0] + sBias2[cc])     * gate;
                    o.y = (acc2[i][j][2 * h + 1] + sBias2[cc + 1]) * gate;
                    *(float2*)(op + cc) = o;
                }
            }
        }
    }
}

// ---------------------------------------------------------------------------
extern "C" void kernel_launch(void* const* d_in, const int* in_sizes, int n_in,
                              void* d_out, int out_size)
{
    const float* x       = (const float*)d_in[0];
    const float* noise   = (const float*)d_in[1];
    const float* w_gate  = (const float*)d_in[2];
    const float* w_noise = (const float*)d_in[3];
    const float* W1      = (const float*)d_in[4];
    const float* b1      = (const float*)d_in[5];
    const float* W2      = (const float*)d_in[6];
    const float* b2      = (const float*)d_in[7];
    float* out = (float*)d_out;

    cudaFuncSetAttribute(gating_kernel, cudaFuncAttributeMaxDynamicSharedMemorySize, G2_SMEM);
    cudaFuncSetAttribute(moe_kernel,    cudaFuncAttributeMaxDynamicSharedMemorySize, SMEM_MOE);

    prep_all_kernel<<<10560, 256>>>((const float4*)x, w_gate, w_noise, W1, W2);
    gating_kernel<<<B_ROWS / 64, 256, G2_SMEM>>>(noise);
    zerofill_kernel<<<B_ROWS * EEXP * 16 / 256, 256>>>((float4*)out);
    moe_kernel<<<dim3(B_ROWS / 128, EEXP), 256, SMEM_MOE>>>(b1, b2, out);
}

// round 16
// speedup vs baseline: 1.1313x; 1.1313x over previous
#include <cuda_runtime.h>
#include <cuda_fp16.h>
#include <cstdint>
#include <math.h>

#define B_ROWS 16384
#define DDIM   512
#define EEXP   16
#define HDIM   256
#define LOUT   64

// ---------------- device scratch (allocation-free rule) ----------------
__device__ float  g_gates[B_ROWS * EEXP];
__device__ int    g_counts[EEXP];
__device__ int    g_rows[EEXP * B_ROWS];
__device__ __half g_Xh [B_ROWS * DDIM];        // x hi, fp16
__device__ __half g_Xlo[B_ROWS * DDIM];        // (x - hi)*2048, fp16
__device__ __half g_W1T[EEXP * HDIM * DDIM];   // [E][H][D], fp16
__device__ __half g_W2T[EEXP * LOUT * HDIM];   // [E][L][H], fp16
__device__ __half g_WcHi[32 * DDIM];           // gating weights [32 cols][512], hi
__device__ __half g_WcLo[32 * DDIM];           // (w - hi)*2048

// ---------------- helpers ----------------
__device__ __forceinline__ uint32_t smem_u32_of(const void* p) {
    uint32_t a;
    asm("{ .reg .u64 t; cvta.to.shared.u64 t, %1; cvt.u32.u64 %0, t; }" : "=r"(a) : "l"(p));
    return a;
}
__device__ __forceinline__ float tanh_fast(float x) {
    float e = __expf(2.f * x);
    return 1.f - __fdividef(2.f, e + 1.f);
}
__device__ __forceinline__ float softplusf(float z) {
    return (z > 0.f) ? (z + log1pf(expf(-z))) : log1pf(expf(z));
}
__device__ __forceinline__ void cp16(uint32_t dst, const void* src) {
    asm volatile("cp.async.ca.shared.global [%0], [%1], 16;" :: "r"(dst), "l"(src));
}
__device__ __forceinline__ void cp16cg(uint32_t dst, const void* src) {
    asm volatile("cp.async.cg.shared.global [%0], [%1], 16;" :: "r"(dst), "l"(src));
}
#define CP_COMMIT() asm volatile("cp.async.commit_group;" ::: "memory")
#define CP_WAIT(n)  asm volatile("cp.async.wait_group %0;" :: "n"(n) : "memory")

#define LDMX4(r0, r1, r2, r3, addr) \
    asm volatile("ldmatrix.sync.aligned.m8n8.x4.shared.b16 {%0,%1,%2,%3}, [%4];" \
                 : "=r"(r0), "=r"(r1), "=r"(r2), "=r"(r3) : "r"(addr))

__device__ __forceinline__ void mma_f16(float* c, const uint32_t* a, const uint32_t* b) {
    asm volatile(
        "mma.sync.aligned.m16n8k16.row.col.f32.f16.f16.f32 "
        "{%0,%1,%2,%3}, {%4,%5,%6,%7}, {%8,%9}, {%0,%1,%2,%3};"
        : "+f"(c[0]), "+f"(c[1]), "+f"(c[2]), "+f"(c[3])
        : "r"(a[0]), "r"(a[1]), "r"(a[2]), "r"(a[3]), "r"(b[0]), "r"(b[1]));
}

// ---------------------------------------------------------------------------
// prep_all: convx split + W1/W2 transposes + gating-weight split + counter
// reset, fused into one launch (block-range switch).
// ---------------------------------------------------------------------------
__device__ __forceinline__ void transpose_tile(const float* __restrict__ s,
                                               __half* __restrict__ d,
                                               int R, int C, int c0, int r0,
                                               float t[32][33], int tx, int ty)
{
    #pragma unroll
    for (int i = 0; i < 32; i += 8)
        t[ty + i][tx] = s[(size_t)(r0 + ty + i) * C + c0 + tx];
    __syncthreads();
    #pragma unroll
    for (int i = 0; i < 32; i += 8)
        d[(size_t)(c0 + ty + i) * R + r0 + tx] = __float2half_rn(t[tx][ty + i]);
}

__global__ __launch_bounds__(256) void prep_all_kernel(
    const float4* __restrict__ x4,
    const float* __restrict__ wg, const float* __restrict__ wn,
    const float* __restrict__ W1, const float* __restrict__ W2)
{
    __shared__ float t[32][33];
    const int b   = blockIdx.x;
    const int tid = threadIdx.x;
    const int tx  = tid & 31;
    const int ty  = tid >> 5;

    if (b < 8192) {
        if (b == 0 && tid < EEXP) g_counts[tid] = 0;
        int i = b * 256 + tid;
        float4 v = x4[i];
        __half hx = __float2half_rn(v.x), hy = __float2half_rn(v.y);
        __half hz = __float2half_rn(v.z), hw = __float2half_rn(v.w);
        __half2* hi = (__half2*)g_Xh;
        __half2* lo = (__half2*)g_Xlo;
        hi[2 * i]     = __halves2half2(hx, hy);
        hi[2 * i + 1] = __halves2half2(hz, hw);
        lo[2 * i]     = __floats2half2_rn((v.x - __half2float(hx)) * 2048.f,
                                          (v.y - __half2float(hy)) * 2048.f);
        lo[2 * i + 1] = __floats2half2_rn((v.z - __half2float(hz)) * 2048.f,
                                          (v.w - __half2float(hw)) * 2048.f);
    } else if (b < 10240) {
        int bb = b - 8192;
        int e = bb >> 7, rem = bb & 127;
        int c0 = (rem & 7) * 32, r0 = (rem >> 3) * 32;
        transpose_tile(W1 + (size_t)e * DDIM * HDIM,
                       g_W1T + (size_t)e * HDIM * DDIM,
                       DDIM, HDIM, c0, r0, t, tx, ty);
    } else if (b < 10496) {
        int bb = b - 10240;
        int e = bb >> 4, rem = bb & 15;
        int c0 = (rem & 1) * 32, r0 = (rem >> 1) * 32;
        transpose_tile(W2 + (size_t)e * HDIM * LOUT,
                       g_W2T + (size_t)e * LOUT * HDIM,
                       HDIM, LOUT, c0, r0, t, tx, ty);
    } else {
        int idx = (b - 10496) * 256 + tid;       // 0..16383
        int j = idx >> 9, d = idx & 511;
        float v = (j < 16) ? wg[d * 16 + j] : wn[d * 16 + (j - 16)];
        __half h = __float2half_rn(v);
        g_WcHi[j * 512 + d] = h;
        g_WcLo[j * 512 + d] = __float2half_rn((v - __half2float(h)) * 2048.f);
    }
}

// ---------------------------------------------------------------------------
// Gating v9: R14's split-fp16 compensated GEMM + integrated sparse zerofill
// of this CTA's own 64 rows (kills the standalone zerofill launch).
// 64 rows/CTA, 256 CTAs, 2 CTAs/SM; fp32-exact epilogue + compaction.
// ---------------------------------------------------------------------------
#define GB_HI   0               // 32*520*2 = 33280
#define GB_LO   33280
#define GA_HI0  66560           // 64*40*2 = 5120 each
#define GA_HI1  71680
#define GA_LO0  76800
#define GA_LO1  81920
#define G_SC    66560           // overlay after GEMM: 64*34*4 = 8704
#define G_LIST  75264           // 16*64 ints = 4096
#define G_CNT   79360
#define G_BASE  79424
#define G_GAT   79488           // 64*16 floats = 4096
#define G2_SMEM 87040

#define GLB  40
#define GLW  520
#define INV2048 4.8828125e-4f

__global__ __launch_bounds__(256, 2) void gating_kernel(const float* __restrict__ noise,
                                                        float4* __restrict__ out4)
{
    extern __shared__ char gsm[];
    const int tid  = threadIdx.x;
    const int wid  = tid >> 5;
    const int lane = tid & 31;
    const int g    = lane >> 2;
    const int tig  = lane & 3;
    const int m0   = blockIdx.x * 64;
    const uint32_t sb = smem_u32_of(gsm);

    const int wm = wid >> 1;
    const int wn = wid & 1;

    const uint32_t offA  = (uint32_t)((lane & 15) * (GLB * 2) + (lane >> 4) * 16);
    const uint32_t offBG = (uint32_t)(((lane & 7) + ((lane >> 4) & 1) * 8) * (GLW * 2) + ((lane >> 3) & 1) * 16);

    #pragma unroll
    for (int t = 0; t < 8; t++) {
        int id = tid + t * 256;
        int r = id >> 6, q = id & 63;
        cp16cg(sb + GB_HI + (uint32_t)(r * (GLW * 2) + q * 16), g_WcHi + r * 512 + q * 8);
        cp16cg(sb + GB_LO + (uint32_t)(r * (GLW * 2) + q * 16), g_WcLo + r * 512 + q * 8);
    }

    auto loadA = [&](int c, int buf) {
        uint32_t hB = sb + (buf ? GA_HI1 : GA_HI0);
        uint32_t lB = sb + (buf ? GA_LO1 : GA_LO0);
        int r = tid >> 2, q = tid & 3;
        cp16(hB + (uint32_t)(r * (GLB * 2) + q * 16),
             g_Xh  + (size_t)(m0 + r) * DDIM + c * 32 + q * 8);
        cp16(lB + (uint32_t)(r * (GLB * 2) + q * 16),
             g_Xlo + (size_t)(m0 + r) * DDIM + c * 32 + q * 8);
    };

    loadA(0, 0);
    CP_COMMIT();

    float acc[2][4], accC[2][4];
    #pragma unroll
    for (int j = 0; j < 2; j++)
        #pragma unroll
        for (int q = 0; q < 4; q++) { acc[j][q] = 0.f; accC[j][q] = 0.f; }

    for (int c = 0; c < 16; c++) {
        int buf = c & 1;
        CP_WAIT(0);
        __syncthreads();
        if (c + 1 < 16) { loadA(c + 1, buf ^ 1); CP_COMMIT(); }

        uint32_t aH = sb + (buf ? GA_HI1 : GA_HI0);
        uint32_t aL = sb + (buf ? GA_LO1 : GA_LO0);

        #pragma unroll
        for (int ks = 0; ks < 32; ks += 16) {
            int kg = c * 32 + ks;
            uint32_t ah[4], al[4], bh[4], bl[4];
            uint32_t oa = (uint32_t)(((wm * 16) * GLB + ks) * 2) + offA;
            LDMX4(ah[0], ah[1], ah[2], ah[3], aH + oa);
            LDMX4(al[0], al[1], al[2], al[3], aL + oa);
            uint32_t ob = (uint32_t)(((wn * 16) * GLW + kg) * 2) + offBG;
            LDMX4(bh[0], bh[1], bh[2], bh[3], sb + GB_HI + ob);
            LDMX4(bl[0], bl[1], bl[2], bl[3], sb + GB_LO + ob);
            mma_f16(acc [0], ah, bh);
            mma_f16(acc [1], ah, bh + 2);
            mma_f16(accC[0], ah, bl);
            mma_f16(accC[1], ah, bl + 2);
            mma_f16(accC[0], al, bh);
            mma_f16(accC[1], al, bh + 2);
        }
    }
    __syncthreads();

    float* sC    = (float*)(gsm + G_SC);
    int*   sList = (int*)(gsm + G_LIST);
    int*   sCnt  = (int*)(gsm + G_CNT);
    int*   sBase = (int*)(gsm + G_BASE);
    float* sGat  = (float*)(gsm + G_GAT);

    {
        int r0 = wm * 16 + g;
        #pragma unroll
        for (int nb = 0; nb < 2; nb++) {
            int cc = wn * 16 + nb * 8 + 2 * tig;
            float2 v0, v1;
            v0.x = acc[nb][0] + accC[nb][0] * INV2048;
            v0.y = acc[nb][1] + accC[nb][1] * INV2048;
            v1.x = acc[nb][2] + accC[nb][2] * INV2048;
            v1.y = acc[nb][3] + accC[nb][3] * INV2048;
            *(float2*)&sC[r0 * 34 + cc]       = v0;
            *(float2*)&sC[(r0 + 8) * 34 + cc] = v1;
        }
    }
    if (tid < EEXP) sCnt[tid] = 0;
    __syncthreads();

    if (tid < 64) {
        int r = m0 + tid;
        float lg[16], p[16];
        float mx = -1e30f;
        #pragma unroll
        for (int j = 0; j < 16; j++) {
            float cl = sC[tid * 34 + j];
            float sd = softplusf(sC[tid * 34 + 16 + j]) + 0.01f;
            lg[j] = fmaf(noise[(size_t)r * EEXP + j], sd, cl);
            mx = fmaxf(mx, lg[j]);
        }
        float s = 0.f;
        #pragma unroll
        for (int j = 0; j < 16; j++) { p[j] = expf(lg[j] - mx); s += p[j]; }
        float s2 = 0.f;
        #pragma unroll
        for (int j = 0; j < 16; j++) { p[j] = p[j] / s; s2 += p[j]; }
        float meanw = s2 * (1.f / 16.f) - 1e-8f;
        float gs = 0.f;
        #pragma unroll
        for (int j = 0; j < 16; j++) {
            p[j] = (p[j] >= meanw) ? p[j] : 0.f;
            gs += p[j];
        }
        #pragma unroll
        for (int j = 0; j < 16; j++) {
            float gv = p[j] / gs;
            g_gates[(size_t)r * EEXP + j] = gv;
            sGat[tid * 16 + j] = p[j];          // 0 iff gate==0
            if (p[j] > 0.f) {
                int idx = atomicAdd(&sCnt[j], 1);
                sList[j * 64 + idx] = r;
            }
        }
    }
    __syncthreads();

    if (tid < EEXP) sBase[tid] = atomicAdd(&g_counts[tid], sCnt[tid]);
    __syncthreads();

    for (int j = 0; j < EEXP; j++) {
        int n = sCnt[j], b = sBase[j];
        for (int i = tid; i < n; i += 256)
            g_rows[j * B_ROWS + b + i] = sList[j * 64 + i];
    }

    // ---- integrated sparse zerofill of this CTA's 64 rows ----
    // slot sl in [0,1024): row = m0 + (sl>>4), e = sl&15;
    // out float4 index = (m0*16 + sl)*16 + q  (16 threads per slot, coalesced)
    const float4 z = make_float4(0.f, 0.f, 0.f, 0.f);
    const size_t outBase = (size_t)m0 * EEXP * 16;
    #pragma unroll 4
    for (int gi = tid; gi < 64 * EEXP * 16; gi += 256) {
        int sl = gi >> 4, q = gi & 15;
        if (sGat[sl] == 0.f)
            out4[outBase + (size_t)sl * 16 + q] = z;
    }
}

// ---------------------------------------------------------------------------
// Fused expert MLP v7 (R14 config — 16 warps, 32x64 tiles — reverted from
// R15's regression). Weight loads via cp.async.cg (L1 bypass).
// ---------------------------------------------------------------------------
#define SM_H     0              // 128*264*2 = 67584
#define SM_A0    67584          // 128*40*2  = 10240 (x3)
#define SM_B0    98304          // 256*40*2  = 20480 (x3)
#define SM_W2    159744         // 64*264*2  = 33792
#define SM_BIAS  193536         // 256f + 64f = 1280
#define SM_ROWS  194816         // 128 ints = 512
#define SMEM_MOE 195328

#define LDK1 40
#define LDH  264
#define LDW2 264

__global__ __launch_bounds__(512, 1) void moe_kernel(
    const float* __restrict__ b1, const float* __restrict__ b2,
    float* __restrict__ out)
{
    extern __shared__ char smem[];
    __half* sH    = (__half*)(smem + SM_H);
    float* sBias1 = (float*)(smem + SM_BIAS);
    float* sBias2 = sBias1 + HDIM;
    int*   sRows  = (int*)(smem + SM_ROWS);

    const int e   = blockIdx.y;
    const int m0  = blockIdx.x * 128;
    const int cnt = g_counts[e];
    if (m0 >= cnt) return;

    const int tid  = threadIdx.x;
    const int wid  = tid >> 5;
    const int lane = tid & 31;
    const int g    = lane >> 2;
    const int tig  = lane & 3;

    const uint32_t smem_b = smem_u32_of(smem);

    const __half* w1e = g_W1T + (size_t)e * HDIM * DDIM;
    const __half* w2e = g_W2T + (size_t)e * LOUT * HDIM;

    if (tid < 128) {
        int p = m0 + tid;
        sRows[tid] = g_rows[e * B_ROWS + (p < cnt ? p : cnt - 1)];
    }
    if (tid < HDIM) sBias1[tid] = b1[(size_t)e * HDIM + tid];
    if (tid < LOUT) sBias2[tid] = b2[(size_t)e * LOUT + tid];
    __syncthreads();   // sRows visible before gathered cp.async

    const uint32_t offA  = (uint32_t)((lane & 15) * (LDK1 * 2) + (lane >> 4) * 16);
    const uint32_t offB  = (uint32_t)(((lane & 7) + ((lane >> 4) & 1) * 8) * (LDK1 * 2) + ((lane >> 3) & 1) * 16);
    const uint32_t offA2 = (uint32_t)((lane & 15) * (LDH * 2) + (lane >> 4) * 16);
    const uint32_t offB2 = (uint32_t)(((lane & 7) + ((lane >> 4) & 1) * 8) * (LDW2 * 2) + ((lane >> 3) & 1) * 16);

    const int wm = wid >> 2;
    const int wn = wid & 3;

    float acc[2][8][4];
    #pragma unroll
    for (int i = 0; i < 2; i++)
        #pragma unroll
        for (int j = 0; j < 8; j++)
            #pragma unroll
            for (int q = 0; q < 4; q++) acc[i][j][q] = 0.f;

    auto load_chunk1 = [&](int c, int buf) {
        uint32_t aBase = smem_b + SM_A0 + buf * 10240;
        uint32_t bBase = smem_b + SM_B0 + buf * 20480;
        {
            int r = tid >> 2, q = tid & 3;
            const __half* src = g_Xh + (size_t)sRows[r] * DDIM + c * 32 + q * 8;
            cp16(aBase + (uint32_t)(r * (LDK1 * 2) + q * 16), src);
        }
        #pragma unroll
        for (int t = 0; t < 2; t++) {
            int id = tid + t * 512;
            int r = id >> 2, q = id & 3;
            cp16cg(bBase + (uint32_t)(r * (LDK1 * 2) + q * 16),
                   w1e + (size_t)r * DDIM + c * 32 + q * 8);
        }
        CP_COMMIT();
    };

    load_chunk1(0, 0);
    load_chunk1(1, 1);

    for (int c = 0; c < 16; c++) {
        int buf = c % 3;
        CP_WAIT(1);
        __syncthreads();
        if (c + 2 < 16) {
            load_chunk1(c + 2, (c + 2) % 3);
        } else if (c + 2 == 16) {
            uint32_t wBase = smem_b + SM_W2;
            #pragma unroll
            for (int t = 0; t < 4; t++) {
                int id = tid + t * 512;
                int r = id >> 5, q = id & 31;
                cp16cg(wBase + (uint32_t)(r * (LDW2 * 2) + q * 16),
                       w2e + (size_t)r * HDIM + q * 8);
            }
            CP_COMMIT();
        }

        const uint32_t aB = smem_b + SM_A0 + buf * 10240;
        const uint32_t bB = smem_b + SM_B0 + buf * 20480;

        #pragma unroll
        for (int ks = 0; ks < 32; ks += 16) {
            uint32_t af[2][4];
            #pragma unroll
            for (int i = 0; i < 2; i++) {
                uint32_t ad = aB + (uint32_t)(((wm * 32 + i * 16) * LDK1 + ks) * 2) + offA;
                LDMX4(af[i][0], af[i][1], af[i][2], af[i][3], ad);
            }
            uint32_t bf[8][2];
            #pragma unroll
            for (int j2 = 0; j2 < 4; j2++) {
                uint32_t bd = bB + (uint32_t)(((wn * 64 + j2 * 16) * LDK1 + ks) * 2) + offB;
                LDMX4(bf[2 * j2][0], bf[2 * j2][1], bf[2 * j2 + 1][0], bf[2 * j2 + 1][1], bd);
            }
            #pragma unroll
            for (int i = 0; i < 2; i++)
                #pragma unroll
                for (int j = 0; j < 8; j++)
                    mma_f16(acc[i][j], af[i], bf[j]);
        }
    }

    // ---- tanh(C1 + b1) -> sH (fp16) ----
    #pragma unroll
    for (int i = 0; i < 2; i++) {
        int r0 = wm * 32 + i * 16 + g;
        #pragma unroll
        for (int j = 0; j < 8; j++) {
            int cc = wn * 64 + j * 8 + 2 * tig;
            float bb0 = sBias1[cc], bb1 = sBias1[cc + 1];
            *(__half2*)&sH[r0 * LDH + cc] =
                __floats2half2_rn(tanh_fast(acc[i][j][0] + bb0), tanh_fast(acc[i][j][1] + bb1));
            *(__half2*)&sH[(r0 + 8) * LDH + cc] =
                __floats2half2_rn(tanh_fast(acc[i][j][2] + bb0), tanh_fast(acc[i][j][3] + bb1));
        }
    }
    CP_WAIT(0);
    __syncthreads();

    // ---- phase 2: 32x16 warp tiles, K=256, barrier-free ----
    const int wm2 = wid >> 2;
    const int wn2 = wid & 3;

    float acc2[2][2][4];
    #pragma unroll
    for (int i = 0; i < 2; i++)
        #pragma unroll
        for (int j = 0; j < 2; j++)
            #pragma unroll
            for (int q = 0; q < 4; q++) acc2[i][j][q] = 0.f;

    const uint32_t hB = smem_b + SM_H;
    const uint32_t wB = smem_b + SM_W2;

    #pragma unroll
    for (int ks = 0; ks < 256; ks += 16) {
        uint32_t af[2][4];
        #pragma unroll
        for (int i = 0; i < 2; i++) {
            uint32_t ad = hB + (uint32_t)(((wm2 * 32 + i * 16) * LDH + ks) * 2) + offA2;
            LDMX4(af[i][0], af[i][1], af[i][2], af[i][3], ad);
        }
        uint32_t bf[4];
        uint32_t bd = wB + (uint32_t)(((wn2 * 16) * LDW2 + ks) * 2) + offB2;
        LDMX4(bf[0], bf[1], bf[2], bf[3], bd);
        #pragma unroll
        for (int i = 0; i < 2; i++) {
            mma_f16(acc2[i][0], af[i], bf);
            mma_f16(acc2[i][1], af[i], bf + 2);
        }
    }

    // ---- epilogue: scatter out[row, e] = gate * (C2 + b2) ----
    #pragma unroll
    for (int i = 0; i < 2; i++) {
        int p0 = wm2 * 32 + i * 16 + g;
        #pragma unroll
        for (int h = 0; h < 2; h++) {
            int p = p0 + h * 8;
            if (m0 + p < cnt) {
                int row = sRows[p];
                float gate = g_gates[(size_t)row * EEXP + e];
                float* op = out + ((size_t)row * EEXP + e) * LOUT;
                #pragma unroll
                for (int j = 0; j < 2; j++) {
                    int cc = wn2 * 16 + j * 8 + 2 * tig;
                    float2 o;
                    o.x = (acc2[i][j][2 * h + 0] + sBias2[cc])     * gate;
                    o.y = (acc2[i][j][2 * h + 1] + sBias2[cc + 1]) * gate;
                    *(float2*)(op + cc) = o;
                }
            }
        }
    }
}

// ---------------------------------------------------------------------------
extern "C" void kernel_launch(void* const* d_in, const int* in_sizes, int n_in,
                              void* d_out, int out_size)
{
    const float* x       = (const float*)d_in[0];
    const float* noise   = (const float*)d_in[1];
    const float* w_gate  = (const float*)d_in[2];
    const float* w_noise = (const float*)d_in[3];
    const float* W1      = (const float*)d_in[4];
    const float* b1      = (const float*)d_in[5];
    const float* W2      = (const float*)d_in[6];
    const float* b2      = (const float*)d_in[7];
    float* out = (float*)d_out;

    cudaFuncSetAttribute(gating_kernel, cudaFuncAttributeMaxDynamicSharedMemorySize, G2_SMEM);
    cudaFuncSetAttribute(moe_kernel,    cudaFuncAttributeMaxDynamicSharedMemorySize, SMEM_MOE);

    prep_all_kernel<<<10560, 256>>>((const float4*)x, w_gate, w_noise, W1, W2);
    gating_kernel<<<B_ROWS / 64, 256, G2_SMEM>>>(noise, (float4*)out);
    moe_kernel<<<dim3(B_ROWS / 128, EEXP), 512, SMEM_MOE>>>(b1, b2, out);
}